// round 13
// baseline (speedup 1.0000x reference)
#include <cuda_runtime.h>
#include <cuda_bf16.h>
#include <cstdint>
#include <math.h>

// ===========================================================================
// GMViT_mini — HMMA (mma.sync bf16) pipeline, 3-term bf16-split.
// R9: new hgemm256 (CTA 128x256, warp tile 64x64, ldsm:mma = 16:96) for the
//     two big GEMMs; hgemm128 retained for small-M GEMMs. Rest frozen.
// ===========================================================================

#define D512 512
#define NVIEWS 20
#define BROWS 4096
#define MROWS (BROWS * NVIEWS)   // 81920

#define OFF_FCNN    0LL
#define OFF_FVIT1   41943040LL
#define OFF_ATT     83886080LL
#define OFF_FVIT2   83968000LL
#define OFF_FGLOB   86065152LL
#define OFF_PRED    88162304LL

typedef unsigned short u16;

// -------------------- scratch (device globals, no allocs) ------------------
__device__ u16   g_fch[(size_t)MROWS * D512];
__device__ u16   g_fcl[(size_t)MROWS * D512];
__device__ float g_x1 [(size_t)MROWS * D512];
__device__ u16   g_sah[(size_t)BROWS * D512];
__device__ u16   g_sal[(size_t)BROWS * D512];
__device__ float g_sb [(size_t)BROWS * D512];
__device__ u16   g_fvh[(size_t)BROWS * D512];
__device__ u16   g_fvl[(size_t)BROWS * D512];
__device__ u16   g_hrh[(size_t)BROWS * D512];
__device__ u16   g_hrl[(size_t)BROWS * D512];
__device__ float g_sc [(size_t)BROWS * 256];
__device__ u16 g_WeTh[512 * 512], g_WeTl[512 * 512];
__device__ u16 g_W1Th[512 * 512], g_W1Tl[512 * 512];
__device__ u16 g_W2Th[512 * 512], g_W2Tl[512 * 512];
__device__ u16 g_h1Th[512 * 512], g_h1Tl[512 * 512];
__device__ u16 g_h2Th[256 * 512], g_h2Tl[256 * 512];

// ============================ helpers ======================================
__device__ __forceinline__ uint32_t smem_u32(const void* p) {
    uint32_t a;
    asm("{ .reg .u64 t; cvta.to.shared.u64 t, %1; cvt.u32.u64 %0, t; }"
        : "=r"(a) : "l"(p));
    return a;
}
#define CP16(d, s) \
    asm volatile("cp.async.cg.shared.global [%0], [%1], 16;" :: "r"(d), "l"(s))
#define CP_COMMIT() asm volatile("cp.async.commit_group;" ::)
#define CP_WAIT0()  asm volatile("cp.async.wait_group 0;" ::)

__device__ __forceinline__ void ldsm4(uint32_t& r0, uint32_t& r1, uint32_t& r2,
                                      uint32_t& r3, uint32_t addr) {
    asm volatile("ldmatrix.sync.aligned.m8n8.x4.shared.b16 {%0,%1,%2,%3}, [%4];"
                 : "=r"(r0), "=r"(r1), "=r"(r2), "=r"(r3) : "r"(addr));
}
__device__ __forceinline__ void mma16816(float* c, const uint32_t* a,
                                         const uint32_t* b) {
    asm volatile(
        "mma.sync.aligned.m16n8k16.row.col.f32.bf16.bf16.f32 "
        "{%0,%1,%2,%3}, {%4,%5,%6,%7}, {%8,%9}, {%0,%1,%2,%3};"
        : "+f"(c[0]), "+f"(c[1]), "+f"(c[2]), "+f"(c[3])
        : "r"(a[0]), "r"(a[1]), "r"(a[2]), "r"(a[3]), "r"(b[0]), "r"(b[1]));
}
__device__ __forceinline__ void split2(float a, float b, uint32_t& hi, uint32_t& lo) {
    __nv_bfloat16 ha = __float2bfloat16(a), hb = __float2bfloat16(b);
    float ra = a - __bfloat162float(ha), rb = b - __bfloat162float(hb);
    __nv_bfloat16 la = __float2bfloat16(ra), lb = __float2bfloat16(rb);
    hi = ((uint32_t)__bfloat16_as_ushort(hb) << 16) | (uint32_t)__bfloat16_as_ushort(ha);
    lo = ((uint32_t)__bfloat16_as_ushort(lb) << 16) | (uint32_t)__bfloat16_as_ushort(la);
}

// ====================== hgemm256 (big GEMMs, M large) ======================
// CTA 128x256, BK=32, 8 warps, warp tile 64x64 (ldsm:mma = 16:96).
// epi 0: C=v    1: C=v; C2h/C2l=split(v)
#define A_TILE2  10240                    // 128 * 80
#define B_TILE2  20480                    // 256 * 80
#define STAGE2   (2 * A_TILE2 + 2 * B_TILE2)   // 61440
#define SMEM_G2  (2 * STAGE2)                  // 122880

__global__ __launch_bounds__(256, 1)
void hgemm256(const float* __restrict__ Af,
              const u16* __restrict__ Ah, const u16* __restrict__ Al,
              const u16* __restrict__ Bh, const u16* __restrict__ Bl,
              const float* __restrict__ bias,
              float* __restrict__ C, u16* __restrict__ C2h, u16* __restrict__ C2l,
              int M, int N, int K, int epi)
{
    extern __shared__ char sm[];
    const int tid  = threadIdx.x;
    const int lane = tid & 31;
    const int wid  = tid >> 5;
    const int wm   = wid >> 2;            // 0..1 (64-row band)
    const int wn   = wid & 3;             // 0..3 (64-col band)
    const int row0 = blockIdx.y * 128;
    const int col0 = blockIdx.x * 256;
    const bool useAf = (Af != nullptr);

    float acc[4][8][4];
#pragma unroll
    for (int i = 0; i < 4; i++)
#pragma unroll
        for (int j = 0; j < 8; j++)
#pragma unroll
            for (int q = 0; q < 4; q++) acc[i][j][q] = 0.0f;

    const int fr = tid >> 1;
    const int fc = (tid & 1) * 16;

    auto load_async = [&](int kb, int buf) {
        const int k0 = kb * 32;
        char* base = sm + buf * STAGE2;
        if (!useAf) {
#pragma unroll
            for (int j = 0; j < 2; j++) {
                int ch = tid + j * 256;              // 0..511
                int r = ch >> 2, c = ch & 3;
                uint32_t d = smem_u32(base + r * 80 + c * 16);
                CP16(d, Ah + (size_t)(row0 + r) * K + k0 + c * 8);
                CP16(d + A_TILE2, Al + (size_t)(row0 + r) * K + k0 + c * 8);
            }
        }
        char* bb = base + 2 * A_TILE2;
#pragma unroll
        for (int j = 0; j < 4; j++) {
            int ch = tid + j * 256;                  // 0..1023
            int r = ch >> 2, c = ch & 3;
            uint32_t d = smem_u32(bb + r * 80 + c * 16);
            CP16(d, Bh + (size_t)(col0 + r) * K + k0 + c * 8);
            CP16(d + B_TILE2, Bl + (size_t)(col0 + r) * K + k0 + c * 8);
        }
    };
    auto ldg_af = [&](int kb, float4* f) {
        const float* p = Af + (size_t)(row0 + fr) * K + kb * 32 + fc;
        f[0] = *(const float4*)p;       f[1] = *(const float4*)(p + 4);
        f[2] = *(const float4*)(p + 8); f[3] = *(const float4*)(p + 12);
    };
    auto sts_af = [&](int buf, const float4* f) {
        char* base = sm + buf * STAGE2;
        uint4 uh0, uh1, ul0, ul1;
        split2(f[0].x, f[0].y, uh0.x, ul0.x);
        split2(f[0].z, f[0].w, uh0.y, ul0.y);
        split2(f[1].x, f[1].y, uh0.z, ul0.z);
        split2(f[1].z, f[1].w, uh0.w, ul0.w);
        split2(f[2].x, f[2].y, uh1.x, ul1.x);
        split2(f[2].z, f[2].w, uh1.y, ul1.y);
        split2(f[3].x, f[3].y, uh1.z, ul1.z);
        split2(f[3].z, f[3].w, uh1.w, ul1.w);
        char* p0 = base + fr * 80 + (fc >> 3) * 16;
        *(uint4*)(p0)                = uh0;
        *(uint4*)(p0 + 16)           = uh1;
        *(uint4*)(p0 + A_TILE2)      = ul0;
        *(uint4*)(p0 + A_TILE2 + 16) = ul1;
    };

    float4 xf[4];
    if (useAf) { ldg_af(0, xf); sts_af(0, xf); }
    load_async(0, 0);
    CP_COMMIT();

    const int nkb = K / 32;
    for (int kb = 0; kb < nkb; kb++) {
        CP_WAIT0();
        __syncthreads();
        if (kb + 1 < nkb) {
            if (useAf) ldg_af(kb + 1, xf);
            load_async(kb + 1, (kb + 1) & 1);
            CP_COMMIT();
        }

        char* base = sm + (kb & 1) * STAGE2;
        const uint32_t sA = smem_u32(base);
        const uint32_t sB = smem_u32(base + 2 * A_TILE2);

#pragma unroll
        for (int ks = 0; ks < 2; ks++) {
            const int k0 = ks * 16;
            uint32_t bh[16], bl[16], ah[4][4], al[4][4];
#pragma unroll
            for (int nt = 0; nt < 4; nt++) {
                int n = wn * 64 + nt * 16 + ((lane >> 4) << 3) + (lane & 7);
                int k = k0 + ((lane >> 3) & 1) * 8;
                uint32_t ad = sB + (uint32_t)(n * 80 + k * 2);
                ldsm4(bh[nt*4+0], bh[nt*4+1], bh[nt*4+2], bh[nt*4+3], ad);
                ldsm4(bl[nt*4+0], bl[nt*4+1], bl[nt*4+2], bl[nt*4+3], ad + B_TILE2);
            }
#pragma unroll
            for (int mi = 0; mi < 4; mi++) {
                int m = wm * 64 + mi * 16 + (lane & 15);
                int k = k0 + (lane >> 4) * 8;
                uint32_t ad = sA + (uint32_t)(m * 80 + k * 2);
                ldsm4(ah[mi][0], ah[mi][1], ah[mi][2], ah[mi][3], ad);
                ldsm4(al[mi][0], al[mi][1], al[mi][2], al[mi][3], ad + A_TILE2);
            }
            // pass-major: dependent mmas 32 issues apart
#pragma unroll
            for (int mi = 0; mi < 4; mi++)
#pragma unroll
                for (int ni = 0; ni < 8; ni++)
                    mma16816(acc[mi][ni], ah[mi], &bh[ni * 2]);
#pragma unroll
            for (int mi = 0; mi < 4; mi++)
#pragma unroll
                for (int ni = 0; ni < 8; ni++)
                    mma16816(acc[mi][ni], ah[mi], &bl[ni * 2]);
#pragma unroll
            for (int mi = 0; mi < 4; mi++)
#pragma unroll
                for (int ni = 0; ni < 8; ni++)
                    mma16816(acc[mi][ni], al[mi], &bh[ni * 2]);
        }
        if (kb + 1 < nkb && useAf) sts_af((kb + 1) & 1, xf);
    }

    // epilogue (epi 0 or 1)
    const int rb = row0 + wm * 64 + (lane >> 2);
    const int cb = col0 + wn * 64 + (lane & 3) * 2;

#pragma unroll
    for (int mi = 0; mi < 4; mi++) {
#pragma unroll
        for (int ni = 0; ni < 8; ni++) {
            const int c = cb + ni * 8;
            float b0 = bias[c], b1 = bias[c + 1];
#pragma unroll
            for (int h = 0; h < 2; h++) {
                const int r = rb + mi * 16 + h * 8;
                float v0 = acc[mi][ni][h * 2 + 0] + b0;
                float v1 = acc[mi][ni][h * 2 + 1] + b1;
                *(float2*)(C + (size_t)r * N + c) = make_float2(v0, v1);
                if (epi == 1) {
                    uint32_t hi, lo;
                    split2(v0, v1, hi, lo);
                    *(uint32_t*)(C2h + (size_t)r * N + c) = hi;
                    *(uint32_t*)(C2l + (size_t)r * N + c) = lo;
                }
            }
        }
    }
}

// ====================== hgemm128 (small-M GEMMs) ===========================
// CTA 128x128, BK=32, 8 warps (64x32), proven R6/R8 path.
// epi 0: C=v    2: w=bn(v); C=w; C2h/C2l=split(relu(w))    3: C=relu(bn(v))
#define TILE_B   10240
#define STAGE_B  (4 * TILE_B)
#define SMEM_G   (2 * STAGE_B)

__global__ __launch_bounds__(256, 2)
void hgemm128(const u16* __restrict__ Ah, const u16* __restrict__ Al,
              const u16* __restrict__ Bh, const u16* __restrict__ Bl,
              const float* __restrict__ bias,
              const float* __restrict__ gamma, const float* __restrict__ beta,
              float* __restrict__ C, u16* __restrict__ C2h, u16* __restrict__ C2l,
              int M, int N, int K, int epi)
{
    extern __shared__ char sm[];
    const int tid  = threadIdx.x;
    const int lane = tid & 31;
    const int wid  = tid >> 5;
    const int wm   = wid >> 2;
    const int wn   = wid & 3;
    const int row0 = blockIdx.y * 128;
    const int col0 = blockIdx.x * 128;

    float acc[4][4][4];
#pragma unroll
    for (int i = 0; i < 4; i++)
#pragma unroll
        for (int j = 0; j < 4; j++)
#pragma unroll
            for (int q = 0; q < 4; q++) acc[i][j][q] = 0.0f;

    auto load_async = [&](int kb, int buf) {
        const int k0 = kb * 32;
        char* base = sm + buf * STAGE_B;
#pragma unroll
        for (int j = 0; j < 2; j++) {
            int ch = tid + j * 256;
            int r = ch >> 2, c = ch & 3;
            uint32_t d = smem_u32(base + r * 80 + c * 16);
            CP16(d, Ah + (size_t)(row0 + r) * K + k0 + c * 8);
            CP16(d + TILE_B, Al + (size_t)(row0 + r) * K + k0 + c * 8);
            uint32_t d2 = smem_u32(base + 2 * TILE_B + r * 80 + c * 16);
            CP16(d2, Bh + (size_t)(col0 + r) * K + k0 + c * 8);
            CP16(d2 + TILE_B, Bl + (size_t)(col0 + r) * K + k0 + c * 8);
        }
    };

    load_async(0, 0);
    CP_COMMIT();

    const int nkb = K / 32;
    for (int kb = 0; kb < nkb; kb++) {
        CP_WAIT0();
        __syncthreads();
        if (kb + 1 < nkb) { load_async(kb + 1, (kb + 1) & 1); CP_COMMIT(); }

        char* base = sm + (kb & 1) * STAGE_B;
        const uint32_t sA = smem_u32(base);
        const uint32_t sB = smem_u32(base + 2 * TILE_B);

#pragma unroll
        for (int ks = 0; ks < 2; ks++) {
            const int k0 = ks * 16;
            uint32_t bh[8], bl[8], ah[4][4], al[4][4];
#pragma unroll
            for (int nt = 0; nt < 2; nt++) {
                int n = wn * 32 + nt * 16 + ((lane >> 4) << 3) + (lane & 7);
                int k = k0 + ((lane >> 3) & 1) * 8;
                uint32_t ad = sB + (uint32_t)(n * 80 + k * 2);
                ldsm4(bh[nt*4+0], bh[nt*4+1], bh[nt*4+2], bh[nt*4+3], ad);
                ldsm4(bl[nt*4+0], bl[nt*4+1], bl[nt*4+2], bl[nt*4+3], ad + TILE_B);
            }
#pragma unroll
            for (int mi = 0; mi < 4; mi++) {
                int m = wm * 64 + mi * 16 + (lane & 15);
                int k = k0 + (lane >> 4) * 8;
                uint32_t ad = sA + (uint32_t)(m * 80 + k * 2);
                ldsm4(ah[mi][0], ah[mi][1], ah[mi][2], ah[mi][3], ad);
                ldsm4(al[mi][0], al[mi][1], al[mi][2], al[mi][3], ad + TILE_B);
            }
#pragma unroll
            for (int mi = 0; mi < 4; mi++)
#pragma unroll
                for (int ni = 0; ni < 4; ni++)
                    mma16816(acc[mi][ni], ah[mi], &bh[ni * 2]);
#pragma unroll
            for (int mi = 0; mi < 4; mi++)
#pragma unroll
                for (int ni = 0; ni < 4; ni++)
                    mma16816(acc[mi][ni], ah[mi], &bl[ni * 2]);
#pragma unroll
            for (int mi = 0; mi < 4; mi++)
#pragma unroll
                for (int ni = 0; ni < 4; ni++)
                    mma16816(acc[mi][ni], al[mi], &bh[ni * 2]);
        }
    }

    const float inv = rsqrtf(1.0f + 1e-5f);
    const int rb = row0 + wm * 64 + (lane >> 2);
    const int cb = col0 + wn * 32 + (lane & 3) * 2;

#pragma unroll
    for (int mi = 0; mi < 4; mi++) {
#pragma unroll
        for (int ni = 0; ni < 4; ni++) {
            const int c = cb + ni * 8;
            float b0 = bias[c], b1 = bias[c + 1];
            float g0 = 0.f, g1 = 0.f, s0 = 0.f, s1 = 0.f;
            if (epi >= 2) { g0 = gamma[c] * inv; g1 = gamma[c+1] * inv;
                            s0 = beta[c];       s1 = beta[c+1]; }
#pragma unroll
            for (int h = 0; h < 2; h++) {
                const int r = rb + mi * 16 + h * 8;
                float v0 = acc[mi][ni][h * 2 + 0] + b0;
                float v1 = acc[mi][ni][h * 2 + 1] + b1;
                if (epi >= 2) { v0 = v0 * g0 + s0; v1 = v1 * g1 + s1; }
                if (epi == 3) { v0 = fmaxf(v0, 0.f); v1 = fmaxf(v1, 0.f); }
                *(float2*)(C + (size_t)r * N + c) = make_float2(v0, v1);
                if (epi == 2) {
                    float w0 = fmaxf(v0, 0.f), w1 = fmaxf(v1, 0.f);
                    uint32_t hi, lo;
                    split2(w0, w1, hi, lo);
                    *(uint32_t*)(C2h + (size_t)r * N + c) = hi;
                    *(uint32_t*)(C2l + (size_t)r * N + c) = lo;
                }
            }
        }
    }
}

// ======= batched weight transpose + bf16 split: W[K,N] -> T[N,K] ===========
__device__ __forceinline__ void wconv_tile(const float* W, u16* Th, u16* Tl,
                                           int N, int n0, int k0, int tx, int ty,
                                           float t[32][33])
{
#pragma unroll
    for (int i = ty; i < 32; i += 8)
        t[i][tx] = W[(size_t)(k0 + i) * N + n0 + tx];
    __syncthreads();
#pragma unroll
    for (int i = ty; i < 32; i += 8) {
        float v = t[tx][i];
        __nv_bfloat16 h = __float2bfloat16(v);
        __nv_bfloat16 l = __float2bfloat16(v - __bfloat162float(h));
        size_t o = (size_t)(n0 + i) * 512 + k0 + tx;
        Th[o] = __bfloat16_as_ushort(h);
        Tl[o] = __bfloat16_as_ushort(l);
    }
}
__global__ __launch_bounds__(256)
void wconv_a(const float* __restrict__ We,  u16* WeTh, u16* WeTl,
             const float* __restrict__ W1,  u16* W1Th, u16* W1Tl,
             const float* __restrict__ W2,  u16* W2Th, u16* W2Tl)
{
    __shared__ float t[32][33];
    const float* W; u16* Th; u16* Tl;
    switch (blockIdx.z) {
        case 0: W = We; Th = WeTh; Tl = WeTl; break;
        case 1: W = W1; Th = W1Th; Tl = W1Tl; break;
        default:W = W2; Th = W2Th; Tl = W2Tl; break;
    }
    wconv_tile(W, Th, Tl, 512, blockIdx.x * 32, blockIdx.y * 32,
               threadIdx.x & 31, threadIdx.x >> 5, t);
}
__global__ __launch_bounds__(256)
void wconv_b(const float* __restrict__ h1W, u16* h1Th, u16* h1Tl,
             const float* __restrict__ h2W, u16* h2Th, u16* h2Tl)
{
    __shared__ float t[32][33];
    if (blockIdx.z == 0) {
        wconv_tile(h1W, h1Th, h1Tl, 512, blockIdx.x * 32, blockIdx.y * 32,
                   threadIdx.x & 31, threadIdx.x >> 5, t);
    } else {
        if (blockIdx.x >= 8) return;
        wconv_tile(h2W, h2Th, h2Tl, 256, blockIdx.x * 32, blockIdx.y * 32,
                   threadIdx.x & 31, threadIdx.x >> 5, t);
    }
}

// ============ fused: LN(x1)+att over 20 views, maxpool + split =============
__global__ __launch_bounds__(640)
void lnpool_kernel(const float* __restrict__ X,
                   const float* __restrict__ g, const float* __restrict__ b,
                   const float* __restrict__ Wa, const float* __restrict__ ba,
                   float* __restrict__ Y, float* __restrict__ att,
                   u16* __restrict__ Ph, u16* __restrict__ Pl)
{
    __shared__ float sx[NVIEWS][D512];
    const int obj  = blockIdx.x;
    const int tid  = threadIdx.x;
    const int w    = tid >> 5;
    const int lane = tid & 31;

    const int row = obj * NVIEWS + w;
    const float* xr = X + (size_t)row * D512;

    float xv[16];
    float s = 0.f, ss = 0.f;
#pragma unroll
    for (int i = 0; i < 16; i++) {
        float v = xr[lane + i * 32];
        xv[i] = v; s += v; ss += v * v;
        sx[w][lane + i * 32] = v;
    }
#pragma unroll
    for (int o = 16; o > 0; o >>= 1) {
        s  += __shfl_xor_sync(0xffffffffu, s,  o);
        ss += __shfl_xor_sync(0xffffffffu, ss, o);
    }
    const float mean = s * (1.0f / 512.0f);
    const float var  = ss * (1.0f / 512.0f) - mean * mean;
    const float rstd = rsqrtf(var + 1e-5f);

    float* yr = Y + (size_t)row * D512;
    float d = 0.f;
#pragma unroll
    for (int i = 0; i < 16; i++) {
        int c = lane + i * 32;
        float y = (xv[i] - mean) * rstd * __ldg(g + c) + __ldg(b + c);
        yr[c] = y;
        d += y * __ldg(Wa + c);
    }
#pragma unroll
    for (int o = 16; o > 0; o >>= 1)
        d += __shfl_xor_sync(0xffffffffu, d, o);
    if (lane == 0)
        att[row] = 1.0f / (1.0f + expf(-(d + ba[0])));

    __syncthreads();
    if (tid < 256) {
        const int c = tid * 2;
        float2 m = *(const float2*)&sx[0][c];
#pragma unroll
        for (int v = 1; v < NVIEWS; v++) {
            float2 t = *(const float2*)&sx[v][c];
            m.x = fmaxf(m.x, t.x); m.y = fmaxf(m.y, t.y);
        }
        uint32_t hi, lo;
        split2(m.x, m.y, hi, lo);
        *(uint32_t*)(Ph + (size_t)obj * D512 + c) = hi;
        *(uint32_t*)(Pl + (size_t)obj * D512 + c) = lo;
    }
}

// ============================ LayerNorm (+split) ===========================
__global__ __launch_bounds__(256)
void ln_kernel(const float* __restrict__ X,
               const float* __restrict__ g, const float* __restrict__ b,
               float* __restrict__ Y, u16* __restrict__ Yh, u16* __restrict__ Yl)
{
    const int row = blockIdx.x;
    const int tid = threadIdx.x;
    const float* xr = X + (size_t)row * D512;

    float x0 = xr[tid], x1 = xr[tid + 256];
    float s = x0 + x1, ss = x0 * x0 + x1 * x1;
#pragma unroll
    for (int o = 16; o > 0; o >>= 1) {
        s  += __shfl_xor_sync(0xffffffffu, s,  o);
        ss += __shfl_xor_sync(0xffffffffu, ss, o);
    }
    __shared__ float rs[8], rss[8];
    const int w = tid >> 5, lane = tid & 31;
    if (lane == 0) { rs[w] = s; rss[w] = ss; }
    __syncthreads();
    float tots = 0.f, totss = 0.f;
#pragma unroll
    for (int i = 0; i < 8; i++) { tots += rs[i]; totss += rss[i]; }
    const float mean = tots * (1.0f / 512.0f);
    const float var  = totss * (1.0f / 512.0f) - mean * mean;
    const float rstd = rsqrtf(var + 1e-5f);
    float y0 = (x0 - mean) * rstd * g[tid]       + b[tid];
    float y1 = (x1 - mean) * rstd * g[tid + 256] + b[tid + 256];
    float* yr = Y + (size_t)row * D512;
    yr[tid] = y0; yr[tid + 256] = y1;

    __nv_bfloat16 h0 = __float2bfloat16(y0);
    __nv_bfloat16 h1 = __float2bfloat16(y1);
    Yh[(size_t)row * D512 + tid]       = __bfloat16_as_ushort(h0);
    Yh[(size_t)row * D512 + tid + 256] = __bfloat16_as_ushort(h1);
    Yl[(size_t)row * D512 + tid]       =
        __bfloat16_as_ushort(__float2bfloat16(y0 - __bfloat162float(h0)));
    Yl[(size_t)row * D512 + tid + 256] =
        __bfloat16_as_ushort(__float2bfloat16(y1 - __bfloat162float(h1)));
}

// ============================ pred =========================================
__global__ void pred_kernel(const float* __restrict__ Hm, const float* __restrict__ W,
                            const float* __restrict__ bias, float* __restrict__ P)
{
    int i = blockIdx.x * blockDim.x + threadIdx.x;
    if (i >= BROWS * 40) return;
    int r = i / 40, n = i % 40;
    const float* h = Hm + (size_t)r * 256;
    float acc = bias[n];
#pragma unroll 8
    for (int k = 0; k < 256; k++)
        acc = fmaf(h[k], W[k * 40 + n], acc);
    P[i] = acc;
}

// ===========================================================================
extern "C" void kernel_launch(void* const* d_in, const int* in_sizes, int n_in,
                              void* d_out, int out_size)
{
    const float* x     = (const float*)d_in[0];
    const float* We    = (const float*)d_in[1];
    const float* be    = (const float*)d_in[2];
    const float* W1    = (const float*)d_in[3];
    const float* b1    = (const float*)d_in[4];
    const float* Wa    = (const float*)d_in[5];
    const float* ba    = (const float*)d_in[6];
    const float* W2    = (const float*)d_in[7];
    const float* b2    = (const float*)d_in[8];
    const float* ln_g  = (const float*)d_in[9];
    const float* ln_b  = (const float*)d_in[10];
    const float* h1W   = (const float*)d_in[11];
    const float* h1b   = (const float*)d_in[12];
    const float* bn1_g = (const float*)d_in[13];
    const float* bn1_b = (const float*)d_in[14];
    const float* h2W   = (const float*)d_in[15];
    const float* h2b   = (const float*)d_in[16];
    const float* bn2_g = (const float*)d_in[17];
    const float* bn2_b = (const float*)d_in[18];
    const float* h3W   = (const float*)d_in[19];
    const float* h3b   = (const float*)d_in[20];

    float* out      = (float*)d_out;
    float* f_cnn    = out + OFF_FCNN;
    float* f_vit1   = out + OFF_FVIT1;
    float* att      = out + OFF_ATT;
    float* f_vit2   = out + OFF_FVIT2;
    float* f_global = out + OFF_FGLOB;
    float* pred     = out + OFF_PRED;

    u16 *fch,*fcl,*sah,*sal,*fvh,*fvl,*hrh,*hrl;
    u16 *WeTh,*WeTl,*W1Th,*W1Tl,*W2Th,*W2Tl,*h1Th,*h1Tl,*h2Th,*h2Tl;
    float *x1s,*sb,*sc;
    { void* p; cudaGetSymbolAddress(&p, g_fch); fch = (u16*)p; }
    { void* p; cudaGetSymbolAddress(&p, g_fcl); fcl = (u16*)p; }
    { void* p; cudaGetSymbolAddress(&p, g_x1);  x1s = (float*)p; }
    { void* p; cudaGetSymbolAddress(&p, g_sah); sah = (u16*)p; }
    { void* p; cudaGetSymbolAddress(&p, g_sal); sal = (u16*)p; }
    { void* p; cudaGetSymbolAddress(&p, g_sb);  sb  = (float*)p; }
    { void* p; cudaGetSymbolAddress(&p, g_fvh); fvh = (u16*)p; }
    { void* p; cudaGetSymbolAddress(&p, g_fvl); fvl = (u16*)p; }
    { void* p; cudaGetSymbolAddress(&p, g_hrh); hrh = (u16*)p; }
    { void* p; cudaGetSymbolAddress(&p, g_hrl); hrl = (u16*)p; }
    { void* p; cudaGetSymbolAddress(&p, g_sc);  sc  = (float*)p; }
    { void* p; cudaGetSymbolAddress(&p, g_WeTh); WeTh = (u16*)p; }
    { void* p; cudaGetSymbolAddress(&p, g_WeTl); WeTl = (u16*)p; }
    { void* p; cudaGetSymbolAddress(&p, g_W1Th); W1Th = (u16*)p; }
    { void* p; cudaGetSymbolAddress(&p, g_W1Tl); W1Tl = (u16*)p; }
    { void* p; cudaGetSymbolAddress(&p, g_W2Th); W2Th = (u16*)p; }
    { void* p; cudaGetSymbolAddress(&p, g_W2Tl); W2Tl = (u16*)p; }
    { void* p; cudaGetSymbolAddress(&p, g_h1Th); h1Th = (u16*)p; }
    { void* p; cudaGetSymbolAddress(&p, g_h1Tl); h1Tl = (u16*)p; }
    { void* p; cudaGetSymbolAddress(&p, g_h2Th); h2Th = (u16*)p; }
    { void* p; cudaGetSymbolAddress(&p, g_h2Tl); h2Tl = (u16*)p; }

    cudaFuncSetAttribute(hgemm256, cudaFuncAttributeMaxDynamicSharedMemorySize, SMEM_G2);
    cudaFuncSetAttribute(hgemm128, cudaFuncAttributeMaxDynamicSharedMemorySize, SMEM_G);

    // launch 1+2: weight transposes+splits
    wconv_a<<<dim3(16, 16, 3), 256>>>(We, WeTh, WeTl, W1, W1Th, W1Tl,
                                      W2, W2Th, W2Tl);
    wconv_b<<<dim3(16, 16, 2), 256>>>(h1W, h1Th, h1Tl, h2W, h2Th, h2Tl);

    // launch 3: K1 f_cnn = x @ We + be  (fp32 A, split emit)
    hgemm256<<<dim3(2, MROWS / 128), 256, SMEM_G2>>>(
        x, nullptr, nullptr, WeTh, WeTl, be,
        f_cnn, fch, fcl, MROWS, D512, D512, 1);

    // launch 4 (ncu target, overall #6): K2 x1 = f_cnn @ W1 + b1
    hgemm256<<<dim3(2, MROWS / 128), 256, SMEM_G2>>>(
        nullptr, fch, fcl, W1Th, W1Tl, b1,
        x1s, nullptr, nullptr, MROWS, D512, D512, 0);

    // launch 5: fused LN + att + maxpool + split
    lnpool_kernel<<<BROWS, 640>>>(x1s, ln_g, ln_b, Wa, ba,
                                  f_vit1, att, sah, sal);

    // launch 6: K5 t = pre @ W2 + b2
    hgemm128<<<dim3(4, BROWS / 128), 256, SMEM_G>>>(
        sah, sal, W2Th, W2Tl, b2, nullptr, nullptr,
        sb, nullptr, nullptr, BROWS, D512, D512, 0);

    // launch 7: f_vit2 = LN(t) (+ split emit)
    ln_kernel<<<BROWS, 256>>>(sb, ln_g, ln_b, f_vit2, fvh, fvl);

    // launch 8: K7 f_global = BN(f_vit2 @ h1W + h1b); split(relu)
    hgemm128<<<dim3(4, BROWS / 128), 256, SMEM_G>>>(
        fvh, fvl, h1Th, h1Tl, h1b, bn1_g, bn1_b,
        f_global, hrh, hrl, BROWS, D512, D512, 2);

    // launch 9: K8 h2 = relu(BN(hr @ h2W + h2b))
    hgemm128<<<dim3(2, BROWS / 128), 256, SMEM_G>>>(
        hrh, hrl, h2Th, h2Tl, h2b, bn2_g, bn2_b,
        sc, nullptr, nullptr, BROWS, 256, D512, 3);

    // launch 10: pred
    pred_kernel<<<(BROWS * 40 + 127) / 128, 128>>>(sc, h3W, h3b, pred);

    (void)in_sizes; (void)n_in; (void)out_size;
}

// round 16
// speedup vs baseline: 1.0534x; 1.0534x over previous
#include <cuda_runtime.h>
#include <cuda_bf16.h>
#include <cstdint>
#include <math.h>

// ===========================================================================
// GMViT_mini — HMMA (mma.sync bf16) pipeline, 3-term bf16-split.
// R10: algebraic K1+K2 fusion. Wc = We@W1 precomputed (fp32); one merged
//      N=1024 GEMM emits f_cnn (cols<512) and x1 (cols>=512) from x.
//      hgemm body = proven R8 kernel + epi5. fch/fcl intermediates removed.
// ===========================================================================

#define D512 512
#define NVIEWS 20
#define BROWS 4096
#define MROWS (BROWS * NVIEWS)   // 81920

#define OFF_FCNN    0LL
#define OFF_FVIT1   41943040LL
#define OFF_ATT     83886080LL
#define OFF_FVIT2   83968000LL
#define OFF_FGLOB   86065152LL
#define OFF_PRED    88162304LL

typedef unsigned short u16;

// -------------------- scratch (device globals, no allocs) ------------------
__device__ float g_x1 [(size_t)MROWS * D512];
__device__ u16   g_sah[(size_t)BROWS * D512];
__device__ u16   g_sal[(size_t)BROWS * D512];
__device__ float g_sb [(size_t)BROWS * D512];
__device__ u16   g_fvh[(size_t)BROWS * D512];
__device__ u16   g_fvl[(size_t)BROWS * D512];
__device__ u16   g_hrh[(size_t)BROWS * D512];
__device__ u16   g_hrl[(size_t)BROWS * D512];
__device__ float g_sc [(size_t)BROWS * 256];
// merged B: rows 0-511 = WeT, rows 512-1023 = WcT = (We@W1)^T
__device__ u16 g_BTh[1024 * 512], g_BTl[1024 * 512];
__device__ u16 g_W2Th[512 * 512], g_W2Tl[512 * 512];
__device__ u16 g_h1Th[512 * 512], g_h1Tl[512 * 512];
__device__ u16 g_h2Th[256 * 512], g_h2Tl[256 * 512];
__device__ float g_bcat[1024];     // [be | b1 + be@W1]

// ============================ helpers ======================================
__device__ __forceinline__ uint32_t smem_u32(const void* p) {
    uint32_t a;
    asm("{ .reg .u64 t; cvta.to.shared.u64 t, %1; cvt.u32.u64 %0, t; }"
        : "=r"(a) : "l"(p));
    return a;
}
#define CP16(d, s) \
    asm volatile("cp.async.cg.shared.global [%0], [%1], 16;" :: "r"(d), "l"(s))
#define CP_COMMIT() asm volatile("cp.async.commit_group;" ::)
#define CP_WAIT0()  asm volatile("cp.async.wait_group 0;" ::)

__device__ __forceinline__ void ldsm4(uint32_t& r0, uint32_t& r1, uint32_t& r2,
                                      uint32_t& r3, uint32_t addr) {
    asm volatile("ldmatrix.sync.aligned.m8n8.x4.shared.b16 {%0,%1,%2,%3}, [%4];"
                 : "=r"(r0), "=r"(r1), "=r"(r2), "=r"(r3) : "r"(addr));
}
__device__ __forceinline__ void mma16816(float* c, const uint32_t* a,
                                         const uint32_t* b) {
    asm volatile(
        "mma.sync.aligned.m16n8k16.row.col.f32.bf16.bf16.f32 "
        "{%0,%1,%2,%3}, {%4,%5,%6,%7}, {%8,%9}, {%0,%1,%2,%3};"
        : "+f"(c[0]), "+f"(c[1]), "+f"(c[2]), "+f"(c[3])
        : "r"(a[0]), "r"(a[1]), "r"(a[2]), "r"(a[3]), "r"(b[0]), "r"(b[1]));
}
__device__ __forceinline__ void split2(float a, float b, uint32_t& hi, uint32_t& lo) {
    __nv_bfloat16 ha = __float2bfloat16(a), hb = __float2bfloat16(b);
    float ra = a - __bfloat162float(ha), rb = b - __bfloat162float(hb);
    __nv_bfloat16 la = __float2bfloat16(ra), lb = __float2bfloat16(rb);
    hi = ((uint32_t)__bfloat16_as_ushort(hb) << 16) | (uint32_t)__bfloat16_as_ushort(ha);
    lo = ((uint32_t)__bfloat16_as_ushort(lb) << 16) | (uint32_t)__bfloat16_as_ushort(la);
}

// ============================ hgemm128 =====================================
// C = (Ah+Al)[M,K] @ (Bh+Bl)[Nb,K]^T + bias   (3-term bf16 split)
// CTA 128x128, BK=32, 8 warps (64x32), cp.async double buffer (R8 body).
// If Af != null, A loaded fp32 and split in-kernel.
// epi 0: C=v
//     2: w=bn(v); C=w;   C2h/C2l = split(relu(w))
//     3: C=relu(bn(v))
//     5: dual concat: col<512 -> C[r*512+c]; col>=512 -> Cx[r*512+c-512]
#define TILE_B   10240
#define STAGE_B  (4 * TILE_B)
#define SMEM_G   (2 * STAGE_B)

__global__ __launch_bounds__(256, 2)
void hgemm128(const float* __restrict__ Af,
              const u16* __restrict__ Ah, const u16* __restrict__ Al,
              const u16* __restrict__ Bh, const u16* __restrict__ Bl,
              const float* __restrict__ bias,
              const float* __restrict__ gamma, const float* __restrict__ beta,
              float* __restrict__ C, float* __restrict__ Cx,
              u16* __restrict__ C2h, u16* __restrict__ C2l,
              int M, int N, int K, int epi)
{
    extern __shared__ char sm[];
    const int tid  = threadIdx.x;
    const int lane = tid & 31;
    const int wid  = tid >> 5;
    const int wm   = wid >> 2;
    const int wn   = wid & 3;
    const int row0 = blockIdx.y * 128;
    const int col0 = blockIdx.x * 128;
    const bool useAf = (Af != nullptr);

    float acc[4][4][4];
#pragma unroll
    for (int i = 0; i < 4; i++)
#pragma unroll
        for (int j = 0; j < 4; j++)
#pragma unroll
            for (int q = 0; q < 4; q++) acc[i][j][q] = 0.0f;

    const int fr = tid >> 1;
    const int fc = (tid & 1) * 16;

    auto load_async = [&](int kb, int buf) {
        const int k0 = kb * 32;
        char* base = sm + buf * STAGE_B;
        if (!useAf) {
#pragma unroll
            for (int j = 0; j < 2; j++) {
                int ch = tid + j * 256;
                int r = ch >> 2, c = ch & 3;
                uint32_t d = smem_u32(base + r * 80 + c * 16);
                CP16(d, Ah + (size_t)(row0 + r) * K + k0 + c * 8);
                CP16(d + TILE_B, Al + (size_t)(row0 + r) * K + k0 + c * 8);
            }
        }
#pragma unroll
        for (int j = 0; j < 2; j++) {
            int ch = tid + j * 256;
            int r = ch >> 2, c = ch & 3;
            uint32_t d = smem_u32(base + 2 * TILE_B + r * 80 + c * 16);
            CP16(d, Bh + (size_t)(col0 + r) * K + k0 + c * 8);
            CP16(d + TILE_B, Bl + (size_t)(col0 + r) * K + k0 + c * 8);
        }
    };
    auto ldg_af = [&](int kb, float4* f) {
        const float* p = Af + (size_t)(row0 + fr) * K + kb * 32 + fc;
        f[0] = *(const float4*)p;       f[1] = *(const float4*)(p + 4);
        f[2] = *(const float4*)(p + 8); f[3] = *(const float4*)(p + 12);
    };
    auto sts_af = [&](int buf, const float4* f) {
        char* base = sm + buf * STAGE_B;
        uint4 uh0, uh1, ul0, ul1;
        split2(f[0].x, f[0].y, uh0.x, ul0.x);
        split2(f[0].z, f[0].w, uh0.y, ul0.y);
        split2(f[1].x, f[1].y, uh0.z, ul0.z);
        split2(f[1].z, f[1].w, uh0.w, ul0.w);
        split2(f[2].x, f[2].y, uh1.x, ul1.x);
        split2(f[2].z, f[2].w, uh1.y, ul1.y);
        split2(f[3].x, f[3].y, uh1.z, ul1.z);
        split2(f[3].z, f[3].w, uh1.w, ul1.w);
        char* p0 = base + fr * 80 + (fc >> 3) * 16;
        *(uint4*)(p0)               = uh0;
        *(uint4*)(p0 + 16)          = uh1;
        *(uint4*)(p0 + TILE_B)      = ul0;
        *(uint4*)(p0 + TILE_B + 16) = ul1;
    };

    float4 xf[4];
    if (useAf) { ldg_af(0, xf); sts_af(0, xf); }
    load_async(0, 0);
    CP_COMMIT();

    const int nkb = K / 32;
    for (int kb = 0; kb < nkb; kb++) {
        CP_WAIT0();
        __syncthreads();
        if (kb + 1 < nkb) {
            if (useAf) ldg_af(kb + 1, xf);
            load_async(kb + 1, (kb + 1) & 1);
            CP_COMMIT();
        }

        char* base = sm + (kb & 1) * STAGE_B;
        const uint32_t sA = smem_u32(base);
        const uint32_t sB = smem_u32(base + 2 * TILE_B);

#pragma unroll
        for (int ks = 0; ks < 2; ks++) {
            const int k0 = ks * 16;
            uint32_t bh[8], bl[8], ah[4][4], al[4][4];
#pragma unroll
            for (int nt = 0; nt < 2; nt++) {
                int n = wn * 32 + nt * 16 + ((lane >> 4) << 3) + (lane & 7);
                int k = k0 + ((lane >> 3) & 1) * 8;
                uint32_t ad = sB + (uint32_t)(n * 80 + k * 2);
                ldsm4(bh[nt*4+0], bh[nt*4+1], bh[nt*4+2], bh[nt*4+3], ad);
                ldsm4(bl[nt*4+0], bl[nt*4+1], bl[nt*4+2], bl[nt*4+3], ad + TILE_B);
            }
#pragma unroll
            for (int mi = 0; mi < 4; mi++) {
                int m = wm * 64 + mi * 16 + (lane & 15);
                int k = k0 + (lane >> 4) * 8;
                uint32_t ad = sA + (uint32_t)(m * 80 + k * 2);
                ldsm4(ah[mi][0], ah[mi][1], ah[mi][2], ah[mi][3], ad);
                ldsm4(al[mi][0], al[mi][1], al[mi][2], al[mi][3], ad + TILE_B);
            }
#pragma unroll
            for (int mi = 0; mi < 4; mi++)
#pragma unroll
                for (int ni = 0; ni < 4; ni++)
                    mma16816(acc[mi][ni], ah[mi], &bh[ni * 2]);
#pragma unroll
            for (int mi = 0; mi < 4; mi++)
#pragma unroll
                for (int ni = 0; ni < 4; ni++)
                    mma16816(acc[mi][ni], ah[mi], &bl[ni * 2]);
#pragma unroll
            for (int mi = 0; mi < 4; mi++)
#pragma unroll
                for (int ni = 0; ni < 4; ni++)
                    mma16816(acc[mi][ni], al[mi], &bh[ni * 2]);
        }
        if (kb + 1 < nkb && useAf) sts_af((kb + 1) & 1, xf);
    }

    // epilogue
    const float inv = rsqrtf(1.0f + 1e-5f);
    const int rb = row0 + wm * 64 + (lane >> 2);
    const int cb = col0 + wn * 32 + (lane & 3) * 2;

    // epi5 routing (whole tile is on one side of col 512)
    float* Co = C;
    int coff = 0;
    if (epi == 5 && col0 >= 512) { Co = Cx; coff = 512; }

#pragma unroll
    for (int mi = 0; mi < 4; mi++) {
#pragma unroll
        for (int ni = 0; ni < 4; ni++) {
            const int c = cb + ni * 8;
            float b0 = bias[c], b1 = bias[c + 1];
            float g0 = 0.f, g1 = 0.f, s0 = 0.f, s1 = 0.f;
            if (epi == 2 || epi == 3) {
                g0 = gamma[c] * inv; g1 = gamma[c+1] * inv;
                s0 = beta[c];        s1 = beta[c+1];
            }
#pragma unroll
            for (int h = 0; h < 2; h++) {
                const int r = rb + mi * 16 + h * 8;
                float v0 = acc[mi][ni][h * 2 + 0] + b0;
                float v1 = acc[mi][ni][h * 2 + 1] + b1;
                if (epi == 2 || epi == 3) { v0 = v0 * g0 + s0; v1 = v1 * g1 + s1; }
                if (epi == 3) { v0 = fmaxf(v0, 0.f); v1 = fmaxf(v1, 0.f); }
                if (epi == 5) {
                    *(float2*)(Co + (size_t)r * 512 + c - coff) = make_float2(v0, v1);
                } else {
                    *(float2*)(C + (size_t)r * N + c) = make_float2(v0, v1);
                }
                if (epi == 2) {
                    float w0 = fmaxf(v0, 0.f), w1 = fmaxf(v1, 0.f);
                    uint32_t hi, lo;
                    split2(w0, w1, hi, lo);
                    *(uint32_t*)(C2h + (size_t)r * N + c) = hi;
                    *(uint32_t*)(C2l + (size_t)r * N + c) = lo;
                }
            }
        }
    }
}

// ================= WcT = (We@W1)^T, bf16-split, into BT rows 512+ ==========
// fp32 tiled GEMM: out[n][k] = sum_j We[k][j] * W1[j][n].
// grid (8,8), block 256 (32 k-lanes x 8 n-rows), 64x64 tile, 2x8 micro.
__global__ __launch_bounds__(256)
void wcT_kernel(const float* __restrict__ We, const float* __restrict__ W1,
                u16* __restrict__ BTh, u16* __restrict__ BTl)
{
    __shared__ float sWe[16][65];   // [j][k]
    __shared__ float sW1[16][65];   // [j][n]
    const int kb = blockIdx.x * 64, nb = blockIdx.y * 64;
    const int tx = threadIdx.x & 31, ty = threadIdx.x >> 5;

    float acc[2][8];
#pragma unroll
    for (int a = 0; a < 2; a++)
#pragma unroll
        for (int b = 0; b < 8; b++) acc[a][b] = 0.0f;

    for (int jb = 0; jb < 512; jb += 16) {
        // load 16x64 tiles (j fast for coalescing-ish)
#pragma unroll
        for (int i = 0; i < 4; i++) {
            int e = threadIdx.x + i * 256;       // 0..1023
            int j = e & 15, q = e >> 4;          // q: 0..63
            sWe[j][q] = We[(size_t)(kb + q) * 512 + jb + j];
            sW1[j][q] = W1[(size_t)(jb + j) * 512 + nb + q];
        }
        __syncthreads();
#pragma unroll
        for (int j = 0; j < 16; j++) {
            float w0 = sWe[j][tx], w1 = sWe[j][tx + 32];
#pragma unroll
            for (int b = 0; b < 8; b++) {
                float u = sW1[j][ty + 8 * b];
                acc[0][b] = fmaf(w0, u, acc[0][b]);
                acc[1][b] = fmaf(w1, u, acc[1][b]);
            }
        }
        __syncthreads();
    }
#pragma unroll
    for (int a = 0; a < 2; a++)
#pragma unroll
        for (int b = 0; b < 8; b++) {
            int n = nb + ty + 8 * b;
            int k = kb + tx + 32 * a;
            float v = acc[a][b];
            __nv_bfloat16 h = __float2bfloat16(v);
            __nv_bfloat16 l = __float2bfloat16(v - __bfloat162float(h));
            size_t o = (size_t)(512 + n) * 512 + k;
            BTh[o] = __bfloat16_as_ushort(h);
            BTl[o] = __bfloat16_as_ushort(l);
        }
}

// ============ bcat = [be | b1 + be@W1]  (1024 floats) ======================
__global__ void bcat_kernel(const float* __restrict__ be, const float* __restrict__ b1,
                            const float* __restrict__ W1, float* __restrict__ bcat)
{
    int i = blockIdx.x * 256 + threadIdx.x;
    if (i >= 1024) return;
    if (i < 512) { bcat[i] = be[i]; return; }
    int n = i - 512;
    float s = b1[n];
    for (int j = 0; j < 512; j++)
        s = fmaf(be[j], W1[(size_t)j * 512 + n], s);
    bcat[i] = s;
}

// ======= batched weight transpose + bf16 split: W[K,N] -> T[N,K] ===========
__device__ __forceinline__ void wconv_tile(const float* W, u16* Th, u16* Tl,
                                           int N, int n0, int k0, int tx, int ty,
                                           float t[32][33])
{
#pragma unroll
    for (int i = ty; i < 32; i += 8)
        t[i][tx] = W[(size_t)(k0 + i) * N + n0 + tx];
    __syncthreads();
#pragma unroll
    for (int i = ty; i < 32; i += 8) {
        float v = t[tx][i];
        __nv_bfloat16 h = __float2bfloat16(v);
        __nv_bfloat16 l = __float2bfloat16(v - __bfloat162float(h));
        size_t o = (size_t)(n0 + i) * 512 + k0 + tx;
        Th[o] = __bfloat16_as_ushort(h);
        Tl[o] = __bfloat16_as_ushort(l);
    }
}
__global__ __launch_bounds__(256)
void wconv_all(const float* __restrict__ We,  u16* BTh, u16* BTl,
               const float* __restrict__ W2,  u16* W2Th, u16* W2Tl,
               const float* __restrict__ h1W, u16* h1Th, u16* h1Tl,
               const float* __restrict__ h2W, u16* h2Th, u16* h2Tl)
{
    __shared__ float t[32][33];
    const float* W; u16* Th; u16* Tl; int N = 512;
    switch (blockIdx.z) {
        case 0: W = We;  Th = BTh;  Tl = BTl;  break;   // BT rows 0-511
        case 1: W = W2;  Th = W2Th; Tl = W2Tl; break;
        case 2: W = h1W; Th = h1Th; Tl = h1Tl; break;
        default:W = h2W; Th = h2Th; Tl = h2Tl; N = 256; break;
    }
    if (blockIdx.x * 32 >= N) return;
    wconv_tile(W, Th, Tl, N, blockIdx.x * 32, blockIdx.y * 32,
               threadIdx.x & 31, threadIdx.x >> 5, t);
}

// ============ fused: LN(x1)+att over 20 views, maxpool + split =============
__global__ __launch_bounds__(640)
void lnpool_kernel(const float* __restrict__ X,
                   const float* __restrict__ g, const float* __restrict__ b,
                   const float* __restrict__ Wa, const float* __restrict__ ba,
                   float* __restrict__ Y, float* __restrict__ att,
                   u16* __restrict__ Ph, u16* __restrict__ Pl)
{
    __shared__ float sx[NVIEWS][D512];
    const int obj  = blockIdx.x;
    const int tid  = threadIdx.x;
    const int w    = tid >> 5;
    const int lane = tid & 31;

    const int row = obj * NVIEWS + w;
    const float* xr = X + (size_t)row * D512;

    float xv[16];
    float s = 0.f, ss = 0.f;
#pragma unroll
    for (int i = 0; i < 16; i++) {
        float v = xr[lane + i * 32];
        xv[i] = v; s += v; ss += v * v;
        sx[w][lane + i * 32] = v;
    }
#pragma unroll
    for (int o = 16; o > 0; o >>= 1) {
        s  += __shfl_xor_sync(0xffffffffu, s,  o);
        ss += __shfl_xor_sync(0xffffffffu, ss, o);
    }
    const float mean = s * (1.0f / 512.0f);
    const float var  = ss * (1.0f / 512.0f) - mean * mean;
    const float rstd = rsqrtf(var + 1e-5f);

    float* yr = Y + (size_t)row * D512;
    float d = 0.f;
#pragma unroll
    for (int i = 0; i < 16; i++) {
        int c = lane + i * 32;
        float y = (xv[i] - mean) * rstd * __ldg(g + c) + __ldg(b + c);
        yr[c] = y;
        d += y * __ldg(Wa + c);
    }
#pragma unroll
    for (int o = 16; o > 0; o >>= 1)
        d += __shfl_xor_sync(0xffffffffu, d, o);
    if (lane == 0)
        att[row] = 1.0f / (1.0f + expf(-(d + ba[0])));

    __syncthreads();
    if (tid < 256) {
        const int c = tid * 2;
        float2 m = *(const float2*)&sx[0][c];
#pragma unroll
        for (int v = 1; v < NVIEWS; v++) {
            float2 t = *(const float2*)&sx[v][c];
            m.x = fmaxf(m.x, t.x); m.y = fmaxf(m.y, t.y);
        }
        uint32_t hi, lo;
        split2(m.x, m.y, hi, lo);
        *(uint32_t*)(Ph + (size_t)obj * D512 + c) = hi;
        *(uint32_t*)(Pl + (size_t)obj * D512 + c) = lo;
    }
}

// ============================ LayerNorm (+split) ===========================
__global__ __launch_bounds__(256)
void ln_kernel(const float* __restrict__ X,
               const float* __restrict__ g, const float* __restrict__ b,
               float* __restrict__ Y, u16* __restrict__ Yh, u16* __restrict__ Yl)
{
    const int row = blockIdx.x;
    const int tid = threadIdx.x;
    const float* xr = X + (size_t)row * D512;

    float x0 = xr[tid], x1 = xr[tid + 256];
    float s = x0 + x1, ss = x0 * x0 + x1 * x1;
#pragma unroll
    for (int o = 16; o > 0; o >>= 1) {
        s  += __shfl_xor_sync(0xffffffffu, s,  o);
        ss += __shfl_xor_sync(0xffffffffu, ss, o);
    }
    __shared__ float rs[8], rss[8];
    const int w = tid >> 5, lane = tid & 31;
    if (lane == 0) { rs[w] = s; rss[w] = ss; }
    __syncthreads();
    float tots = 0.f, totss = 0.f;
#pragma unroll
    for (int i = 0; i < 8; i++) { tots += rs[i]; totss += rss[i]; }
    const float mean = tots * (1.0f / 512.0f);
    const float var  = totss * (1.0f / 512.0f) - mean * mean;
    const float rstd = rsqrtf(var + 1e-5f);
    float y0 = (x0 - mean) * rstd * g[tid]       + b[tid];
    float y1 = (x1 - mean) * rstd * g[tid + 256] + b[tid + 256];
    float* yr = Y + (size_t)row * D512;
    yr[tid] = y0; yr[tid + 256] = y1;

    __nv_bfloat16 h0 = __float2bfloat16(y0);
    __nv_bfloat16 h1 = __float2bfloat16(y1);
    Yh[(size_t)row * D512 + tid]       = __bfloat16_as_ushort(h0);
    Yh[(size_t)row * D512 + tid + 256] = __bfloat16_as_ushort(h1);
    Yl[(size_t)row * D512 + tid]       =
        __bfloat16_as_ushort(__float2bfloat16(y0 - __bfloat162float(h0)));
    Yl[(size_t)row * D512 + tid + 256] =
        __bfloat16_as_ushort(__float2bfloat16(y1 - __bfloat162float(h1)));
}

// ============================ pred =========================================
__global__ void pred_kernel(const float* __restrict__ Hm, const float* __restrict__ W,
                            const float* __restrict__ bias, float* __restrict__ P)
{
    int i = blockIdx.x * blockDim.x + threadIdx.x;
    if (i >= BROWS * 40) return;
    int r = i / 40, n = i % 40;
    const float* h = Hm + (size_t)r * 256;
    float acc = bias[n];
#pragma unroll 8
    for (int k = 0; k < 256; k++)
        acc = fmaf(h[k], W[k * 40 + n], acc);
    P[i] = acc;
}

// ===========================================================================
extern "C" void kernel_launch(void* const* d_in, const int* in_sizes, int n_in,
                              void* d_out, int out_size)
{
    const float* x     = (const float*)d_in[0];
    const float* We    = (const float*)d_in[1];
    const float* be    = (const float*)d_in[2];
    const float* W1    = (const float*)d_in[3];
    const float* b1    = (const float*)d_in[4];
    const float* Wa    = (const float*)d_in[5];
    const float* ba    = (const float*)d_in[6];
    const float* W2    = (const float*)d_in[7];
    const float* b2    = (const float*)d_in[8];
    const float* ln_g  = (const float*)d_in[9];
    const float* ln_b  = (const float*)d_in[10];
    const float* h1W   = (const float*)d_in[11];
    const float* h1b   = (const float*)d_in[12];
    const float* bn1_g = (const float*)d_in[13];
    const float* bn1_b = (const float*)d_in[14];
    const float* h2W   = (const float*)d_in[15];
    const float* h2b   = (const float*)d_in[16];
    const float* bn2_g = (const float*)d_in[17];
    const float* bn2_b = (const float*)d_in[18];
    const float* h3W   = (const float*)d_in[19];
    const float* h3b   = (const float*)d_in[20];

    float* out      = (float*)d_out;
    float* f_cnn    = out + OFF_FCNN;
    float* f_vit1   = out + OFF_FVIT1;
    float* att      = out + OFF_ATT;
    float* f_vit2   = out + OFF_FVIT2;
    float* f_global = out + OFF_FGLOB;
    float* pred     = out + OFF_PRED;

    u16 *sah,*sal,*fvh,*fvl,*hrh,*hrl;
    u16 *BTh,*BTl,*W2Th,*W2Tl,*h1Th,*h1Tl,*h2Th,*h2Tl;
    float *x1s,*sb,*sc,*bcat;
    { void* p; cudaGetSymbolAddress(&p, g_x1);  x1s = (float*)p; }
    { void* p; cudaGetSymbolAddress(&p, g_sah); sah = (u16*)p; }
    { void* p; cudaGetSymbolAddress(&p, g_sal); sal = (u16*)p; }
    { void* p; cudaGetSymbolAddress(&p, g_sb);  sb  = (float*)p; }
    { void* p; cudaGetSymbolAddress(&p, g_fvh); fvh = (u16*)p; }
    { void* p; cudaGetSymbolAddress(&p, g_fvl); fvl = (u16*)p; }
    { void* p; cudaGetSymbolAddress(&p, g_hrh); hrh = (u16*)p; }
    { void* p; cudaGetSymbolAddress(&p, g_hrl); hrl = (u16*)p; }
    { void* p; cudaGetSymbolAddress(&p, g_sc);  sc  = (float*)p; }
    { void* p; cudaGetSymbolAddress(&p, g_BTh); BTh = (u16*)p; }
    { void* p; cudaGetSymbolAddress(&p, g_BTl); BTl = (u16*)p; }
    { void* p; cudaGetSymbolAddress(&p, g_W2Th); W2Th = (u16*)p; }
    { void* p; cudaGetSymbolAddress(&p, g_W2Tl); W2Tl = (u16*)p; }
    { void* p; cudaGetSymbolAddress(&p, g_h1Th); h1Th = (u16*)p; }
    { void* p; cudaGetSymbolAddress(&p, g_h1Tl); h1Tl = (u16*)p; }
    { void* p; cudaGetSymbolAddress(&p, g_h2Th); h2Th = (u16*)p; }
    { void* p; cudaGetSymbolAddress(&p, g_h2Tl); h2Tl = (u16*)p; }
    { void* p; cudaGetSymbolAddress(&p, g_bcat); bcat = (float*)p; }

    cudaFuncSetAttribute(hgemm128, cudaFuncAttributeMaxDynamicSharedMemorySize, SMEM_G);

    // launch 1: WcT = (We@W1)^T split -> BT rows 512-1023
    wcT_kernel<<<dim3(8, 8), 256>>>(We, W1, BTh, BTl);
    // launch 2: bcat = [be | b1 + be@W1]
    bcat_kernel<<<4, 256>>>(be, b1, W1, bcat);
    // launch 3: WeT -> BT rows 0-511; W2T, h1T, h2T
    wconv_all<<<dim3(16, 16, 4), 256>>>(We, BTh, BTl, W2, W2Th, W2Tl,
                                        h1W, h1Th, h1Tl, h2W, h2Th, h2Tl);

    // launch 4 (ncu target, overall #6): merged GEMM
    //   cols 0-511: f_cnn = x@We+be      cols 512-1023: x1 = x@Wc+bc
    hgemm128<<<dim3(8, MROWS / 128), 256, SMEM_G>>>(
        x, nullptr, nullptr, BTh, BTl, bcat, nullptr, nullptr,
        f_cnn, x1s, nullptr, nullptr, MROWS, 512, D512, 5);

    // launch 5: fused LN + att + maxpool + split
    lnpool_kernel<<<BROWS, 640>>>(x1s, ln_g, ln_b, Wa, ba,
                                  f_vit1, att, sah, sal);

    // launch 6: t = pre @ W2 + b2
    hgemm128<<<dim3(4, BROWS / 128), 256, SMEM_G>>>(
        nullptr, sah, sal, W2Th, W2Tl, b2, nullptr, nullptr,
        sb, nullptr, nullptr, nullptr, BROWS, D512, D512, 0);

    // launch 7: f_vit2 = LN(t) (+ split emit)
    ln_kernel<<<BROWS, 256>>>(sb, ln_g, ln_b, f_vit2, fvh, fvl);

    // launch 8: f_global = BN(f_vit2 @ h1W + h1b); split(relu) -> hrh/hrl
    hgemm128<<<dim3(4, BROWS / 128), 256, SMEM_G>>>(
        nullptr, fvh, fvl, h1Th, h1Tl, h1b, bn1_g, bn1_b,
        f_global, nullptr, hrh, hrl, BROWS, D512, D512, 2);

    // launch 9: h2 = relu(BN(hr @ h2W + h2b))
    hgemm128<<<dim3(2, BROWS / 128), 256, SMEM_G>>>(
        nullptr, hrh, hrl, h2Th, h2Tl, h2b, bn2_g, bn2_b,
        sc, nullptr, nullptr, nullptr, BROWS, 256, D512, 3);

    // launch 10: pred
    pred_kernel<<<(BROWS * 40 + 127) / 128, 128>>>(sc, h3W, h3b, pred);

    (void)in_sizes; (void)n_in; (void)out_size;
}

// round 17
// speedup vs baseline: 1.1431x; 1.0851x over previous
#include <cuda_runtime.h>
#include <cuda_bf16.h>
#include <cstdint>
#include <math.h>

// ===========================================================================
// GMViT_mini — HMMA (mma.sync bf16) pipeline, 3-term bf16-split.
// R11: revert to R8 big-GEMM path; add hgemm64 (CTA 64x128) so small GEMMs
//      get 2 CTAs/SM; wconv merged to one launch (lnpool becomes profiled).
// ===========================================================================

#define D512 512
#define NVIEWS 20
#define BROWS 4096
#define MROWS (BROWS * NVIEWS)   // 81920

#define OFF_FCNN    0LL
#define OFF_FVIT1   41943040LL
#define OFF_ATT     83886080LL
#define OFF_FVIT2   83968000LL
#define OFF_FGLOB   86065152LL
#define OFF_PRED    88162304LL

typedef unsigned short u16;

// -------------------- scratch (device globals, no allocs) ------------------
__device__ u16   g_fch[(size_t)MROWS * D512];
__device__ u16   g_fcl[(size_t)MROWS * D512];
__device__ float g_x1 [(size_t)MROWS * D512];
__device__ u16   g_sah[(size_t)BROWS * D512];
__device__ u16   g_sal[(size_t)BROWS * D512];
__device__ float g_sb [(size_t)BROWS * D512];
__device__ u16   g_fvh[(size_t)BROWS * D512];
__device__ u16   g_fvl[(size_t)BROWS * D512];
__device__ u16   g_hrh[(size_t)BROWS * D512];
__device__ u16   g_hrl[(size_t)BROWS * D512];
__device__ float g_sc [(size_t)BROWS * 256];
__device__ u16 g_WeTh[512 * 512], g_WeTl[512 * 512];
__device__ u16 g_W1Th[512 * 512], g_W1Tl[512 * 512];
__device__ u16 g_W2Th[512 * 512], g_W2Tl[512 * 512];
__device__ u16 g_h1Th[512 * 512], g_h1Tl[512 * 512];
__device__ u16 g_h2Th[256 * 512], g_h2Tl[256 * 512];

// ============================ helpers ======================================
__device__ __forceinline__ uint32_t smem_u32(const void* p) {
    uint32_t a;
    asm("{ .reg .u64 t; cvta.to.shared.u64 t, %1; cvt.u32.u64 %0, t; }"
        : "=r"(a) : "l"(p));
    return a;
}
#define CP16(d, s) \
    asm volatile("cp.async.cg.shared.global [%0], [%1], 16;" :: "r"(d), "l"(s))
#define CP_COMMIT() asm volatile("cp.async.commit_group;" ::)
#define CP_WAIT0()  asm volatile("cp.async.wait_group 0;" ::)

__device__ __forceinline__ void ldsm4(uint32_t& r0, uint32_t& r1, uint32_t& r2,
                                      uint32_t& r3, uint32_t addr) {
    asm volatile("ldmatrix.sync.aligned.m8n8.x4.shared.b16 {%0,%1,%2,%3}, [%4];"
                 : "=r"(r0), "=r"(r1), "=r"(r2), "=r"(r3) : "r"(addr));
}
__device__ __forceinline__ void mma16816(float* c, const uint32_t* a,
                                         const uint32_t* b) {
    asm volatile(
        "mma.sync.aligned.m16n8k16.row.col.f32.bf16.bf16.f32 "
        "{%0,%1,%2,%3}, {%4,%5,%6,%7}, {%8,%9}, {%0,%1,%2,%3};"
        : "+f"(c[0]), "+f"(c[1]), "+f"(c[2]), "+f"(c[3])
        : "r"(a[0]), "r"(a[1]), "r"(a[2]), "r"(a[3]), "r"(b[0]), "r"(b[1]));
}
__device__ __forceinline__ void split2(float a, float b, uint32_t& hi, uint32_t& lo) {
    __nv_bfloat16 ha = __float2bfloat16(a), hb = __float2bfloat16(b);
    float ra = a - __bfloat162float(ha), rb = b - __bfloat162float(hb);
    __nv_bfloat16 la = __float2bfloat16(ra), lb = __float2bfloat16(rb);
    hi = ((uint32_t)__bfloat16_as_ushort(hb) << 16) | (uint32_t)__bfloat16_as_ushort(ha);
    lo = ((uint32_t)__bfloat16_as_ushort(lb) << 16) | (uint32_t)__bfloat16_as_ushort(la);
}

// ============================ hgemm (R8 body) ==============================
// C[M,N] = (Ah+Al)[M,K] @ (Bh+Bl)[N,K]^T + bias   (3-term bf16 split)
// CTA 128x128, BK=32, 8 warps (64x32), cp.async double buffer.
// If Af != null, A loaded fp32 and split in-kernel.
// epi 0: C=v    1: C=v; C2h/C2l=split(v)
#define TILE_B   10240
#define STAGE_B  (4 * TILE_B)
#define SMEM_G   (2 * STAGE_B)

__global__ __launch_bounds__(256, 2)
void hgemm(const float* __restrict__ Af,
           const u16* __restrict__ Ah, const u16* __restrict__ Al,
           const u16* __restrict__ Bh, const u16* __restrict__ Bl,
           const float* __restrict__ bias,
           float* __restrict__ C, u16* __restrict__ C2h, u16* __restrict__ C2l,
           int M, int N, int K, int epi)
{
    extern __shared__ char sm[];
    const int tid  = threadIdx.x;
    const int lane = tid & 31;
    const int wid  = tid >> 5;
    const int wm   = wid >> 2;
    const int wn   = wid & 3;
    const int row0 = blockIdx.y * 128;
    const int col0 = blockIdx.x * 128;
    const bool useAf = (Af != nullptr);

    float acc[4][4][4];
#pragma unroll
    for (int i = 0; i < 4; i++)
#pragma unroll
        for (int j = 0; j < 4; j++)
#pragma unroll
            for (int q = 0; q < 4; q++) acc[i][j][q] = 0.0f;

    const int fr = tid >> 1;
    const int fc = (tid & 1) * 16;

    auto load_async = [&](int kb, int buf) {
        const int k0 = kb * 32;
        char* base = sm + buf * STAGE_B;
        if (!useAf) {
#pragma unroll
            for (int j = 0; j < 2; j++) {
                int ch = tid + j * 256;
                int r = ch >> 2, c = ch & 3;
                uint32_t d = smem_u32(base + r * 80 + c * 16);
                CP16(d, Ah + (size_t)(row0 + r) * K + k0 + c * 8);
                CP16(d + TILE_B, Al + (size_t)(row0 + r) * K + k0 + c * 8);
            }
        }
#pragma unroll
        for (int j = 0; j < 2; j++) {
            int ch = tid + j * 256;
            int r = ch >> 2, c = ch & 3;
            uint32_t d = smem_u32(base + 2 * TILE_B + r * 80 + c * 16);
            CP16(d, Bh + (size_t)(col0 + r) * K + k0 + c * 8);
            CP16(d + TILE_B, Bl + (size_t)(col0 + r) * K + k0 + c * 8);
        }
    };
    auto ldg_af = [&](int kb, float4* f) {
        const float* p = Af + (size_t)(row0 + fr) * K + kb * 32 + fc;
        f[0] = *(const float4*)p;       f[1] = *(const float4*)(p + 4);
        f[2] = *(const float4*)(p + 8); f[3] = *(const float4*)(p + 12);
    };
    auto sts_af = [&](int buf, const float4* f) {
        char* base = sm + buf * STAGE_B;
        uint4 uh0, uh1, ul0, ul1;
        split2(f[0].x, f[0].y, uh0.x, ul0.x);
        split2(f[0].z, f[0].w, uh0.y, ul0.y);
        split2(f[1].x, f[1].y, uh0.z, ul0.z);
        split2(f[1].z, f[1].w, uh0.w, ul0.w);
        split2(f[2].x, f[2].y, uh1.x, ul1.x);
        split2(f[2].z, f[2].w, uh1.y, ul1.y);
        split2(f[3].x, f[3].y, uh1.z, ul1.z);
        split2(f[3].z, f[3].w, uh1.w, ul1.w);
        char* p0 = base + fr * 80 + (fc >> 3) * 16;
        *(uint4*)(p0)               = uh0;
        *(uint4*)(p0 + 16)          = uh1;
        *(uint4*)(p0 + TILE_B)      = ul0;
        *(uint4*)(p0 + TILE_B + 16) = ul1;
    };

    float4 xf[4];
    if (useAf) { ldg_af(0, xf); sts_af(0, xf); }
    load_async(0, 0);
    CP_COMMIT();

    const int nkb = K / 32;
    for (int kb = 0; kb < nkb; kb++) {
        CP_WAIT0();
        __syncthreads();
        if (kb + 1 < nkb) {
            if (useAf) ldg_af(kb + 1, xf);
            load_async(kb + 1, (kb + 1) & 1);
            CP_COMMIT();
        }

        char* base = sm + (kb & 1) * STAGE_B;
        const uint32_t sA = smem_u32(base);
        const uint32_t sB = smem_u32(base + 2 * TILE_B);

#pragma unroll
        for (int ks = 0; ks < 2; ks++) {
            const int k0 = ks * 16;
            uint32_t bh[8], bl[8], ah[4][4], al[4][4];
#pragma unroll
            for (int nt = 0; nt < 2; nt++) {
                int n = wn * 32 + nt * 16 + ((lane >> 4) << 3) + (lane & 7);
                int k = k0 + ((lane >> 3) & 1) * 8;
                uint32_t ad = sB + (uint32_t)(n * 80 + k * 2);
                ldsm4(bh[nt*4+0], bh[nt*4+1], bh[nt*4+2], bh[nt*4+3], ad);
                ldsm4(bl[nt*4+0], bl[nt*4+1], bl[nt*4+2], bl[nt*4+3], ad + TILE_B);
            }
#pragma unroll
            for (int mi = 0; mi < 4; mi++) {
                int m = wm * 64 + mi * 16 + (lane & 15);
                int k = k0 + (lane >> 4) * 8;
                uint32_t ad = sA + (uint32_t)(m * 80 + k * 2);
                ldsm4(ah[mi][0], ah[mi][1], ah[mi][2], ah[mi][3], ad);
                ldsm4(al[mi][0], al[mi][1], al[mi][2], al[mi][3], ad + TILE_B);
            }
#pragma unroll
            for (int mi = 0; mi < 4; mi++)
#pragma unroll
                for (int ni = 0; ni < 4; ni++)
                    mma16816(acc[mi][ni], ah[mi], &bh[ni * 2]);
#pragma unroll
            for (int mi = 0; mi < 4; mi++)
#pragma unroll
                for (int ni = 0; ni < 4; ni++)
                    mma16816(acc[mi][ni], ah[mi], &bl[ni * 2]);
#pragma unroll
            for (int mi = 0; mi < 4; mi++)
#pragma unroll
                for (int ni = 0; ni < 4; ni++)
                    mma16816(acc[mi][ni], al[mi], &bh[ni * 2]);
        }
        if (kb + 1 < nkb && useAf) sts_af((kb + 1) & 1, xf);
    }

    const int rb = row0 + wm * 64 + (lane >> 2);
    const int cb = col0 + wn * 32 + (lane & 3) * 2;

#pragma unroll
    for (int mi = 0; mi < 4; mi++) {
#pragma unroll
        for (int ni = 0; ni < 4; ni++) {
            const int c = cb + ni * 8;
            float b0 = bias[c], b1 = bias[c + 1];
#pragma unroll
            for (int h = 0; h < 2; h++) {
                const int r = rb + mi * 16 + h * 8;
                float v0 = acc[mi][ni][h * 2 + 0] + b0;
                float v1 = acc[mi][ni][h * 2 + 1] + b1;
                *(float2*)(C + (size_t)r * N + c) = make_float2(v0, v1);
                if (epi == 1) {
                    uint32_t hi, lo;
                    split2(v0, v1, hi, lo);
                    *(uint32_t*)(C2h + (size_t)r * N + c) = hi;
                    *(uint32_t*)(C2l + (size_t)r * N + c) = lo;
                }
            }
        }
    }
}

// ====================== hgemm64 (small-M GEMMs) ============================
// CTA 64x128, BK=32, 8 warps (warp tile 32x32). Doubles CTA count for
// M=4096 GEMMs -> ~2 CTAs/SM coverage.
// epi 0: C=v    2: w=bn(v); C=w; C2h/C2l=split(relu(w))    3: C=relu(bn(v))
#define A_T64   5120                       // 64 * 80
#define B_T64   10240                      // 128 * 80
#define STAGE64 (2 * A_T64 + 2 * B_T64)    // 30720
#define SMEM_64 (2 * STAGE64)              // 61440

__global__ __launch_bounds__(256, 2)
void hgemm64(const u16* __restrict__ Ah, const u16* __restrict__ Al,
             const u16* __restrict__ Bh, const u16* __restrict__ Bl,
             const float* __restrict__ bias,
             const float* __restrict__ gamma, const float* __restrict__ beta,
             float* __restrict__ C, u16* __restrict__ C2h, u16* __restrict__ C2l,
             int M, int N, int K, int epi)
{
    extern __shared__ char sm[];
    const int tid  = threadIdx.x;
    const int lane = tid & 31;
    const int wid  = tid >> 5;
    const int wm   = wid >> 2;            // 0..1 (32-row band)
    const int wn   = wid & 3;             // 0..3 (32-col band)
    const int row0 = blockIdx.y * 64;
    const int col0 = blockIdx.x * 128;

    float acc[2][4][4];
#pragma unroll
    for (int i = 0; i < 2; i++)
#pragma unroll
        for (int j = 0; j < 4; j++)
#pragma unroll
            for (int q = 0; q < 4; q++) acc[i][j][q] = 0.0f;

    auto load_async = [&](int kb, int buf) {
        const int k0 = kb * 32;
        char* base = sm + buf * STAGE64;
        {   // A: 64 rows x 4 chunks = 256
            int r = tid >> 2, c = tid & 3;
            uint32_t d = smem_u32(base + r * 80 + c * 16);
            CP16(d, Ah + (size_t)(row0 + r) * K + k0 + c * 8);
            CP16(d + A_T64, Al + (size_t)(row0 + r) * K + k0 + c * 8);
        }
        char* bb = base + 2 * A_T64;
#pragma unroll
        for (int j = 0; j < 2; j++) {     // B: 128 rows x 4 chunks = 512
            int ch = tid + j * 256;
            int r = ch >> 2, c = ch & 3;
            uint32_t d = smem_u32(bb + r * 80 + c * 16);
            CP16(d, Bh + (size_t)(col0 + r) * K + k0 + c * 8);
            CP16(d + B_T64, Bl + (size_t)(col0 + r) * K + k0 + c * 8);
        }
    };

    load_async(0, 0);
    CP_COMMIT();

    const int nkb = K / 32;
    for (int kb = 0; kb < nkb; kb++) {
        CP_WAIT0();
        __syncthreads();
        if (kb + 1 < nkb) { load_async(kb + 1, (kb + 1) & 1); CP_COMMIT(); }

        char* base = sm + (kb & 1) * STAGE64;
        const uint32_t sA = smem_u32(base);
        const uint32_t sB = smem_u32(base + 2 * A_T64);

#pragma unroll
        for (int ks = 0; ks < 2; ks++) {
            const int k0 = ks * 16;
            uint32_t bh[8], bl[8], ah[2][4], al[2][4];
#pragma unroll
            for (int nt = 0; nt < 2; nt++) {
                int n = wn * 32 + nt * 16 + ((lane >> 4) << 3) + (lane & 7);
                int k = k0 + ((lane >> 3) & 1) * 8;
                uint32_t ad = sB + (uint32_t)(n * 80 + k * 2);
                ldsm4(bh[nt*4+0], bh[nt*4+1], bh[nt*4+2], bh[nt*4+3], ad);
                ldsm4(bl[nt*4+0], bl[nt*4+1], bl[nt*4+2], bl[nt*4+3], ad + B_T64);
            }
#pragma unroll
            for (int mi = 0; mi < 2; mi++) {
                int m = wm * 32 + mi * 16 + (lane & 15);
                int k = k0 + (lane >> 4) * 8;
                uint32_t ad = sA + (uint32_t)(m * 80 + k * 2);
                ldsm4(ah[mi][0], ah[mi][1], ah[mi][2], ah[mi][3], ad);
                ldsm4(al[mi][0], al[mi][1], al[mi][2], al[mi][3], ad + A_T64);
            }
#pragma unroll
            for (int mi = 0; mi < 2; mi++)
#pragma unroll
                for (int ni = 0; ni < 4; ni++)
                    mma16816(acc[mi][ni], ah[mi], &bh[ni * 2]);
#pragma unroll
            for (int mi = 0; mi < 2; mi++)
#pragma unroll
                for (int ni = 0; ni < 4; ni++)
                    mma16816(acc[mi][ni], ah[mi], &bl[ni * 2]);
#pragma unroll
            for (int mi = 0; mi < 2; mi++)
#pragma unroll
                for (int ni = 0; ni < 4; ni++)
                    mma16816(acc[mi][ni], al[mi], &bh[ni * 2]);
        }
    }

    const float inv = rsqrtf(1.0f + 1e-5f);
    const int rb = row0 + wm * 32 + (lane >> 2);
    const int cb = col0 + wn * 32 + (lane & 3) * 2;

#pragma unroll
    for (int mi = 0; mi < 2; mi++) {
#pragma unroll
        for (int ni = 0; ni < 4; ni++) {
            const int c = cb + ni * 8;
            float b0 = bias[c], b1 = bias[c + 1];
            float g0 = 0.f, g1 = 0.f, s0 = 0.f, s1 = 0.f;
            if (epi >= 2) { g0 = gamma[c] * inv; g1 = gamma[c+1] * inv;
                            s0 = beta[c];       s1 = beta[c+1]; }
#pragma unroll
            for (int h = 0; h < 2; h++) {
                const int r = rb + mi * 16 + h * 8;
                float v0 = acc[mi][ni][h * 2 + 0] + b0;
                float v1 = acc[mi][ni][h * 2 + 1] + b1;
                if (epi >= 2) { v0 = v0 * g0 + s0; v1 = v1 * g1 + s1; }
                if (epi == 3) { v0 = fmaxf(v0, 0.f); v1 = fmaxf(v1, 0.f); }
                *(float2*)(C + (size_t)r * N + c) = make_float2(v0, v1);
                if (epi == 2) {
                    float w0 = fmaxf(v0, 0.f), w1 = fmaxf(v1, 0.f);
                    uint32_t hi, lo;
                    split2(w0, w1, hi, lo);
                    *(uint32_t*)(C2h + (size_t)r * N + c) = hi;
                    *(uint32_t*)(C2l + (size_t)r * N + c) = lo;
                }
            }
        }
    }
}

// ======= batched weight transpose + bf16 split: W[K,N] -> T[N,K] ===========
__device__ __forceinline__ void wconv_tile(const float* W, u16* Th, u16* Tl,
                                           int N, int n0, int k0, int tx, int ty,
                                           float t[32][33])
{
#pragma unroll
    for (int i = ty; i < 32; i += 8)
        t[i][tx] = W[(size_t)(k0 + i) * N + n0 + tx];
    __syncthreads();
#pragma unroll
    for (int i = ty; i < 32; i += 8) {
        float v = t[tx][i];
        __nv_bfloat16 h = __float2bfloat16(v);
        __nv_bfloat16 l = __float2bfloat16(v - __bfloat162float(h));
        size_t o = (size_t)(n0 + i) * 512 + k0 + tx;
        Th[o] = __bfloat16_as_ushort(h);
        Tl[o] = __bfloat16_as_ushort(l);
    }
}
__global__ __launch_bounds__(256)
void wconv_all(const float* __restrict__ We,  u16* WeTh, u16* WeTl,
               const float* __restrict__ W1,  u16* W1Th, u16* W1Tl,
               const float* __restrict__ W2,  u16* W2Th, u16* W2Tl,
               const float* __restrict__ h1W, u16* h1Th, u16* h1Tl,
               const float* __restrict__ h2W, u16* h2Th, u16* h2Tl)
{
    __shared__ float t[32][33];
    const float* W; u16* Th; u16* Tl; int N = 512;
    switch (blockIdx.z) {
        case 0: W = We;  Th = WeTh; Tl = WeTl; break;
        case 1: W = W1;  Th = W1Th; Tl = W1Tl; break;
        case 2: W = W2;  Th = W2Th; Tl = W2Tl; break;
        case 3: W = h1W; Th = h1Th; Tl = h1Tl; break;
        default:W = h2W; Th = h2Th; Tl = h2Tl; N = 256; break;
    }
    if (blockIdx.x * 32 >= N) return;
    wconv_tile(W, Th, Tl, N, blockIdx.x * 32, blockIdx.y * 32,
               threadIdx.x & 31, threadIdx.x >> 5, t);
}

// ============ fused: LN(x1)+att over 20 views, maxpool + split =============
__global__ __launch_bounds__(640)
void lnpool_kernel(const float* __restrict__ X,
                   const float* __restrict__ g, const float* __restrict__ b,
                   const float* __restrict__ Wa, const float* __restrict__ ba,
                   float* __restrict__ Y, float* __restrict__ att,
                   u16* __restrict__ Ph, u16* __restrict__ Pl)
{
    __shared__ float sx[NVIEWS][D512];
    const int obj  = blockIdx.x;
    const int tid  = threadIdx.x;
    const int w    = tid >> 5;
    const int lane = tid & 31;

    const int row = obj * NVIEWS + w;
    const float* xr = X + (size_t)row * D512;

    float xv[16];
    float s = 0.f, ss = 0.f;
#pragma unroll
    for (int i = 0; i < 16; i++) {
        float v = xr[lane + i * 32];
        xv[i] = v; s += v; ss += v * v;
        sx[w][lane + i * 32] = v;
    }
#pragma unroll
    for (int o = 16; o > 0; o >>= 1) {
        s  += __shfl_xor_sync(0xffffffffu, s,  o);
        ss += __shfl_xor_sync(0xffffffffu, ss, o);
    }
    const float mean = s * (1.0f / 512.0f);
    const float var  = ss * (1.0f / 512.0f) - mean * mean;
    const float rstd = rsqrtf(var + 1e-5f);

    float* yr = Y + (size_t)row * D512;
    float d = 0.f;
#pragma unroll
    for (int i = 0; i < 16; i++) {
        int c = lane + i * 32;
        float y = (xv[i] - mean) * rstd * __ldg(g + c) + __ldg(b + c);
        yr[c] = y;
        d += y * __ldg(Wa + c);
    }
#pragma unroll
    for (int o = 16; o > 0; o >>= 1)
        d += __shfl_xor_sync(0xffffffffu, d, o);
    if (lane == 0)
        att[row] = 1.0f / (1.0f + expf(-(d + ba[0])));

    __syncthreads();
    if (tid < 256) {
        const int c = tid * 2;
        float2 m = *(const float2*)&sx[0][c];
#pragma unroll
        for (int v = 1; v < NVIEWS; v++) {
            float2 t = *(const float2*)&sx[v][c];
            m.x = fmaxf(m.x, t.x); m.y = fmaxf(m.y, t.y);
        }
        uint32_t hi, lo;
        split2(m.x, m.y, hi, lo);
        *(uint32_t*)(Ph + (size_t)obj * D512 + c) = hi;
        *(uint32_t*)(Pl + (size_t)obj * D512 + c) = lo;
    }
}

// ============================ LayerNorm (+split) ===========================
__global__ __launch_bounds__(256)
void ln_kernel(const float* __restrict__ X,
               const float* __restrict__ g, const float* __restrict__ b,
               float* __restrict__ Y, u16* __restrict__ Yh, u16* __restrict__ Yl)
{
    const int row = blockIdx.x;
    const int tid = threadIdx.x;
    const float* xr = X + (size_t)row * D512;

    float x0 = xr[tid], x1 = xr[tid + 256];
    float s = x0 + x1, ss = x0 * x0 + x1 * x1;
#pragma unroll
    for (int o = 16; o > 0; o >>= 1) {
        s  += __shfl_xor_sync(0xffffffffu, s,  o);
        ss += __shfl_xor_sync(0xffffffffu, ss, o);
    }
    __shared__ float rs[8], rss[8];
    const int w = tid >> 5, lane = tid & 31;
    if (lane == 0) { rs[w] = s; rss[w] = ss; }
    __syncthreads();
    float tots = 0.f, totss = 0.f;
#pragma unroll
    for (int i = 0; i < 8; i++) { tots += rs[i]; totss += rss[i]; }
    const float mean = tots * (1.0f / 512.0f);
    const float var  = totss * (1.0f / 512.0f) - mean * mean;
    const float rstd = rsqrtf(var + 1e-5f);
    float y0 = (x0 - mean) * rstd * g[tid]       + b[tid];
    float y1 = (x1 - mean) * rstd * g[tid + 256] + b[tid + 256];
    float* yr = Y + (size_t)row * D512;
    yr[tid] = y0; yr[tid + 256] = y1;

    __nv_bfloat16 h0 = __float2bfloat16(y0);
    __nv_bfloat16 h1 = __float2bfloat16(y1);
    Yh[(size_t)row * D512 + tid]       = __bfloat16_as_ushort(h0);
    Yh[(size_t)row * D512 + tid + 256] = __bfloat16_as_ushort(h1);
    Yl[(size_t)row * D512 + tid]       =
        __bfloat16_as_ushort(__float2bfloat16(y0 - __bfloat162float(h0)));
    Yl[(size_t)row * D512 + tid + 256] =
        __bfloat16_as_ushort(__float2bfloat16(y1 - __bfloat162float(h1)));
}

// ============================ pred =========================================
__global__ void pred_kernel(const float* __restrict__ Hm, const float* __restrict__ W,
                            const float* __restrict__ bias, float* __restrict__ P)
{
    int i = blockIdx.x * blockDim.x + threadIdx.x;
    if (i >= BROWS * 40) return;
    int r = i / 40, n = i % 40;
    const float* h = Hm + (size_t)r * 256;
    float acc = bias[n];
#pragma unroll 8
    for (int k = 0; k < 256; k++)
        acc = fmaf(h[k], W[k * 40 + n], acc);
    P[i] = acc;
}

// ===========================================================================
extern "C" void kernel_launch(void* const* d_in, const int* in_sizes, int n_in,
                              void* d_out, int out_size)
{
    const float* x     = (const float*)d_in[0];
    const float* We    = (const float*)d_in[1];
    const float* be    = (const float*)d_in[2];
    const float* W1    = (const float*)d_in[3];
    const float* b1    = (const float*)d_in[4];
    const float* Wa    = (const float*)d_in[5];
    const float* ba    = (const float*)d_in[6];
    const float* W2    = (const float*)d_in[7];
    const float* b2    = (const float*)d_in[8];
    const float* ln_g  = (const float*)d_in[9];
    const float* ln_b  = (const float*)d_in[10];
    const float* h1W   = (const float*)d_in[11];
    const float* h1b   = (const float*)d_in[12];
    const float* bn1_g = (const float*)d_in[13];
    const float* bn1_b = (const float*)d_in[14];
    const float* h2W   = (const float*)d_in[15];
    const float* h2b   = (const float*)d_in[16];
    const float* bn2_g = (const float*)d_in[17];
    const float* bn2_b = (const float*)d_in[18];
    const float* h3W   = (const float*)d_in[19];
    const float* h3b   = (const float*)d_in[20];

    float* out      = (float*)d_out;
    float* f_cnn    = out + OFF_FCNN;
    float* f_vit1   = out + OFF_FVIT1;
    float* att      = out + OFF_ATT;
    float* f_vit2   = out + OFF_FVIT2;
    float* f_global = out + OFF_FGLOB;
    float* pred     = out + OFF_PRED;

    u16 *fch,*fcl,*sah,*sal,*fvh,*fvl,*hrh,*hrl;
    u16 *WeTh,*WeTl,*W1Th,*W1Tl,*W2Th,*W2Tl,*h1Th,*h1Tl,*h2Th,*h2Tl;
    float *x1s,*sb,*sc;
    { void* p; cudaGetSymbolAddress(&p, g_fch); fch = (u16*)p; }
    { void* p; cudaGetSymbolAddress(&p, g_fcl); fcl = (u16*)p; }
    { void* p; cudaGetSymbolAddress(&p, g_x1);  x1s = (float*)p; }
    { void* p; cudaGetSymbolAddress(&p, g_sah); sah = (u16*)p; }
    { void* p; cudaGetSymbolAddress(&p, g_sal); sal = (u16*)p; }
    { void* p; cudaGetSymbolAddress(&p, g_sb);  sb  = (float*)p; }
    { void* p; cudaGetSymbolAddress(&p, g_fvh); fvh = (u16*)p; }
    { void* p; cudaGetSymbolAddress(&p, g_fvl); fvl = (u16*)p; }
    { void* p; cudaGetSymbolAddress(&p, g_hrh); hrh = (u16*)p; }
    { void* p; cudaGetSymbolAddress(&p, g_hrl); hrl = (u16*)p; }
    { void* p; cudaGetSymbolAddress(&p, g_sc);  sc  = (float*)p; }
    { void* p; cudaGetSymbolAddress(&p, g_WeTh); WeTh = (u16*)p; }
    { void* p; cudaGetSymbolAddress(&p, g_WeTl); WeTl = (u16*)p; }
    { void* p; cudaGetSymbolAddress(&p, g_W1Th); W1Th = (u16*)p; }
    { void* p; cudaGetSymbolAddress(&p, g_W1Tl); W1Tl = (u16*)p; }
    { void* p; cudaGetSymbolAddress(&p, g_W2Th); W2Th = (u16*)p; }
    { void* p; cudaGetSymbolAddress(&p, g_W2Tl); W2Tl = (u16*)p; }
    { void* p; cudaGetSymbolAddress(&p, g_h1Th); h1Th = (u16*)p; }
    { void* p; cudaGetSymbolAddress(&p, g_h1Tl); h1Tl = (u16*)p; }
    { void* p; cudaGetSymbolAddress(&p, g_h2Th); h2Th = (u16*)p; }
    { void* p; cudaGetSymbolAddress(&p, g_h2Tl); h2Tl = (u16*)p; }

    cudaFuncSetAttribute(hgemm,   cudaFuncAttributeMaxDynamicSharedMemorySize, SMEM_G);
    cudaFuncSetAttribute(hgemm64, cudaFuncAttributeMaxDynamicSharedMemorySize, SMEM_64);

    // launch 1: all weight transposes+splits
    wconv_all<<<dim3(16, 16, 5), 256>>>(We, WeTh, WeTl, W1, W1Th, W1Tl,
                                        W2, W2Th, W2Tl, h1W, h1Th, h1Tl,
                                        h2W, h2Th, h2Tl);

    // launch 2: K1 f_cnn = x @ We + be  (fp32 A, split emit)
    hgemm<<<dim3(4, MROWS / 128), 256, SMEM_G>>>(
        x, nullptr, nullptr, WeTh, WeTl, be,
        f_cnn, fch, fcl, MROWS, D512, D512, 1);

    // launch 3: K2 x1 = f_cnn @ W1 + b1
    hgemm<<<dim3(4, MROWS / 128), 256, SMEM_G>>>(
        nullptr, fch, fcl, W1Th, W1Tl, b1,
        x1s, nullptr, nullptr, MROWS, D512, D512, 0);

    // launch 4 (ncu target, overall #6): fused LN + att + maxpool + split
    lnpool_kernel<<<BROWS, 640>>>(x1s, ln_g, ln_b, Wa, ba,
                                  f_vit1, att, sah, sal);

    // launch 5: K5 t = pre @ W2 + b2   (64-row tiles -> 256 CTAs)
    hgemm64<<<dim3(4, BROWS / 64), 256, SMEM_64>>>(
        sah, sal, W2Th, W2Tl, b2, nullptr, nullptr,
        sb, nullptr, nullptr, BROWS, D512, D512, 0);

    // launch 6: f_vit2 = LN(t) (+ split emit)
    ln_kernel<<<BROWS, 256>>>(sb, ln_g, ln_b, f_vit2, fvh, fvl);

    // launch 7: K7 f_global = BN(f_vit2 @ h1W + h1b); split(relu)
    hgemm64<<<dim3(4, BROWS / 64), 256, SMEM_64>>>(
        fvh, fvl, h1Th, h1Tl, h1b, bn1_g, bn1_b,
        f_global, hrh, hrl, BROWS, D512, D512, 2);

    // launch 8: K8 h2 = relu(BN(hr @ h2W + h2b))
    hgemm64<<<dim3(2, BROWS / 64), 256, SMEM_64>>>(
        hrh, hrl, h2Th, h2Tl, h2b, bn2_g, bn2_b,
        sc, nullptr, nullptr, BROWS, 256, D512, 3);

    // launch 9: pred
    pred_kernel<<<(BROWS * 40 + 127) / 128, 128>>>(sc, h3W, h3b, pred);

    (void)in_sizes; (void)n_in; (void)out_size;
}